// round 1
// baseline (speedup 1.0000x reference)
#include <cuda_runtime.h>
#include <math.h>

// Problem constants
#define NB   512          // graphs
#define NPG  128          // nodes per graph (stage 1)
#define DEG  16
#define EPG  2048         // edges per graph
#define ETOT 1048576
#define KP1  103          // ceil(0.8*128)
#define KP2  83           // ceil(0.8*103)

// ---- global scratch (static __device__ arrays; no allocation) ----
__device__ float g_h1p[NB * KP1 * 32];   // pooled (scaled) features after pool1
__device__ int   g_edge2[NB * EPG];      // packed (ns<<8)|nd surviving edges
__device__ int   g_ecnt[NB];             // surviving edge count per graph
__device__ float g_g1[NB * 64];          // readout after pool1
__device__ float g_gf[NB * 64];          // g1 + g2

static __device__ __forceinline__ float lrelu(float v) { return v > 0.f ? v : 0.2f * v; }

// ============================================================================
// Stage 1: GAT conv 1 + linear + TopK pool 1 + readout g1 + edge remap.
// One CTA (256 threads) per graph; everything in shared memory.
// ============================================================================
__global__ __launch_bounds__(256, 1)
void stage1_kernel(const float* __restrict__ x, const int* __restrict__ ei,
                   const float* __restrict__ Wg, const float* __restrict__ as_w,
                   const float* __restrict__ ad_w, const float* __restrict__ bg,
                   const float* __restrict__ Wt, const float* __restrict__ bt,
                   const float* __restrict__ pw)
{
    extern __shared__ char sm[];
    float* xp   = (float*)sm;            // [128*128] node features after W_g1
    float* outt = xp + 16384;            // [128*128] conv output (post relu)
    float* asv  = outt + 16384;          // [128*4]
    float* adv  = asv + 512;             // [128*4]
    float* lg   = adv + 512;             // [2048*4] logits -> ex ; later h [128*32]
    float* hsh  = lg;
    char*  p    = (char*)(lg + 8192);
    unsigned short* eidx = (unsigned short*)p; p += EPG * 2;   // CSR edge ids
    unsigned char*  srcl = (unsigned char*)p;  p += EPG;
    unsigned char*  dstl = (unsigned char*)p;  p += EPG;
    int*   cnt  = (int*)p;  p += 128 * 4;
    int*   offs = (int*)p;  p += 132 * 4;
    float* Wgs  = (float*)p; p += 11 * 128 * 4;
    float* Wts  = (float*)p; p += 128 * 32 * 4;
    float* score= (float*)p; p += 128 * 4;
    int*   nidx = (int*)p;  p += 128 * 4;
    float* wn   = (float*)p; p += 4;
    int*   ec   = (int*)p;

    const int g = blockIdx.x, t = threadIdx.x;
    const int lane = t & 31, warp = t >> 5;

    for (int i = t; i < 11 * 128; i += 256) Wgs[i] = Wg[i];
    for (int i = t; i < 128 * 32; i += 256) Wts[i] = Wt[i];
    if (t == 0) {
        float s = 0.f;
        for (int k = 0; k < 32; k++) s += pw[k] * pw[k];
        *wn = sqrtf(s); *ec = 0;
    }
    if (t < 128) cnt[t] = 0;
    __syncthreads();

    // xp = x @ W_g1   [128 x 128]
    for (int i = t; i < 128 * 128; i += 256) {
        int n = i >> 7, c = i & 127;
        const float* xr = x + (size_t)(g * NPG + n) * 11;
        float a = 0.f;
        #pragma unroll
        for (int k = 0; k < 11; k++) a += xr[k] * Wgs[k * 128 + c];
        xp[i] = a;
    }
    __syncthreads();

    // per-node, per-head attention terms
    for (int i = t; i < 128 * 4; i += 256) {
        int n = i >> 2, h = i & 3;
        float a = 0.f, b = 0.f;
        #pragma unroll
        for (int c = 0; c < 32; c++) {
            float v = xp[n * 128 + h * 32 + c];
            a += v * as_w[h * 32 + c];
            b += v * ad_w[h * 32 + c];
        }
        asv[i] = a; adv[i] = b;
    }
    __syncthreads();

    // edge load + logits + dst counts
    for (int e = t; e < EPG; e += 256) {
        int s = ei[g * EPG + e] - g * NPG;
        int d = ei[ETOT + g * EPG + e] - g * NPG;
        srcl[e] = (unsigned char)s; dstl[e] = (unsigned char)d;
        atomicAdd(&cnt[d], 1);
        float4 l4;
        l4.x = lrelu(asv[s * 4 + 0] + adv[d * 4 + 0]);
        l4.y = lrelu(asv[s * 4 + 1] + adv[d * 4 + 1]);
        l4.z = lrelu(asv[s * 4 + 2] + adv[d * 4 + 2]);
        l4.w = lrelu(asv[s * 4 + 3] + adv[d * 4 + 3]);
        *(float4*)&lg[e * 4] = l4;
    }
    __syncthreads();
    if (t == 0) {
        int a = 0;
        for (int n = 0; n < 128; n++) { offs[n] = a; a += cnt[n]; cnt[n] = 0; }
        offs[128] = a;
    }
    __syncthreads();
    for (int e = t; e < EPG; e += 256) {
        int d = dstl[e];
        eidx[offs[d] + atomicAdd(&cnt[d], 1)] = (unsigned short)e;
    }
    __syncthreads();

    // per-dst-node softmax + aggregation: one warp per node
    for (int d = warp; d < 128; d += 8) {
        int o0 = offs[d], dg = offs[d + 1] - o0;
        float sl[4];
        #pragma unroll
        for (int h = 0; h < 4; h++) sl[h] = lrelu(asv[d * 4 + h] + adv[d * 4 + h]);
        int hh = lane & 3;
        float mmax = -1e30f;
        for (int b = lane >> 2; b < dg; b += 8)
            mmax = fmaxf(mmax, lg[eidx[o0 + b] * 4 + hh]);
        for (int m = 4; m < 32; m <<= 1)
            mmax = fmaxf(mmax, __shfl_xor_sync(0xffffffffu, mmax, m));
        float mx[4];
        #pragma unroll
        for (int h = 0; h < 4; h++)
            mx[h] = fmaxf(__shfl_sync(0xffffffffu, mmax, h), sl[h]);
        float md = 0.f;
        for (int b = lane >> 2; b < dg; b += 8) {
            int e = eidx[o0 + b];
            float ex = expf(lg[e * 4 + hh] - mx[hh]);
            lg[e * 4 + hh] = ex;           // overwrite logit with ex (unique owner)
            md += ex;
        }
        for (int m = 4; m < 32; m <<= 1)
            md += __shfl_xor_sync(0xffffffffu, md, m);
        float den[4], acc[4];
        #pragma unroll
        for (int h = 0; h < 4; h++) {
            float se = expf(sl[h] - mx[h]);
            den[h] = __shfl_sync(0xffffffffu, md, h) + se + 1e-16f;
            acc[h] = se * xp[d * 128 + h * 32 + lane];
        }
        __syncwarp();
        for (int k2 = 0; k2 < dg; k2++) {
            int e = eidx[o0 + k2]; int s = srcl[e];
            float4 ex4 = *(const float4*)&lg[e * 4];
            acc[0] += ex4.x * xp[s * 128 +   0 + lane];
            acc[1] += ex4.y * xp[s * 128 +  32 + lane];
            acc[2] += ex4.z * xp[s * 128 +  64 + lane];
            acc[3] += ex4.w * xp[s * 128 +  96 + lane];
        }
        #pragma unroll
        for (int j = 0; j < 4; j++) {
            float v = acc[j] / den[j] + bg[j * 32 + lane];
            outt[d * 128 + j * 32 + lane] = fmaxf(v, 0.f);
        }
    }
    __syncthreads();

    // h = relu(conv) @ W_t1 + b_t1    (hsh aliases logits region, safe now)
    for (int i = t; i < 128 * 32; i += 256) {
        int n = i >> 5, o = i & 31;
        float a = bt[o];
        const float* orow = &outt[n * 128];
        #pragma unroll 4
        for (int c = 0; c < 128; c++) a += orow[c] * Wts[c * 32 + o];
        hsh[i] = a;
    }
    __syncthreads();

    // pool scores
    if (t < 128) {
        float s = 0.f;
        #pragma unroll
        for (int o = 0; o < 32; o++) s += hsh[t * 32 + o] * pw[o];
        score[t] = tanhf(s / (*wn));
    }
    __syncthreads();
    // top-K1 selection: rank (matches stable top_k tie-break)
    if (t < 128) {
        float sc = score[t]; int r = 0;
        for (int m = 0; m < 128; m++) {
            float v = score[m];
            r += (v > sc) || (v == sc && m < t);
        }
        nidx[t] = (r < KP1) ? 0 : -1;
    }
    __syncthreads();
    if (t == 0) {
        int c2 = 0;
        for (int n = 0; n < 128; n++) if (nidx[n] == 0) nidx[n] = c2++;
    }
    __syncthreads();

    // pooled (scaled) features + g1 readout + remapped edges
    for (int i = t; i < 128 * 32; i += 256) {
        int n = i >> 5, o = i & 31, ni = nidx[n];
        if (ni >= 0) g_h1p[((size_t)g * KP1 + ni) * 32 + o] = hsh[i] * score[n];
    }
    if (t < 32) {
        float m2 = -1e30f, su = 0.f;
        for (int n = 0; n < 128; n++) if (nidx[n] >= 0) {
            float v = hsh[n * 32 + t] * score[n];
            m2 = fmaxf(m2, v); su += v;
        }
        g_g1[g * 64 + t] = m2;
        g_g1[g * 64 + 32 + t] = su / (float)KP1;
    }
    for (int e = t; e < EPG; e += 256) {
        int ns = nidx[srcl[e]], nd = nidx[dstl[e]];
        if (ns >= 0 && nd >= 0)
            g_edge2[g * EPG + atomicAdd(ec, 1)] = (ns << 8) | nd;
    }
    __syncthreads();
    if (t == 0) g_ecnt[g] = *ec;
}

// ============================================================================
// Stage 2: GAT conv 2 + linear + TopK pool 2 + readout; writes g = g1+g2.
// ============================================================================
__global__ __launch_bounds__(256, 1)
void stage2_kernel(const float* __restrict__ Wg, const float* __restrict__ as_w,
                   const float* __restrict__ ad_w, const float* __restrict__ bg,
                   const float* __restrict__ Wt, const float* __restrict__ bt,
                   const float* __restrict__ pw)
{
    extern __shared__ char sm[];
    float* tile = (float*)sm;            // [103*32]
    float* xp   = tile + KP1 * 32;       // [103*128]
    float* outt = xp + KP1 * 128;        // [103*128]
    float* asv  = outt + KP1 * 128;      // [103*4]
    float* adv  = asv + KP1 * 4;         // [103*4]
    float* lg   = adv + KP1 * 4;         // [2048*4] ; later h [103*32]
    float* hsh  = lg;
    float* Wgs  = lg + 8192;             // [32*128]
    float* Wts  = Wgs + 4096;            // [128*32]
    char*  p    = (char*)(Wts + 4096);
    unsigned short* eidx = (unsigned short*)p; p += EPG * 2;
    unsigned char*  srcl = (unsigned char*)p;  p += EPG;
    unsigned char*  dstl = (unsigned char*)p;  p += EPG;
    int*   cnt  = (int*)p;  p += 104 * 4;
    int*   offs = (int*)p;  p += 104 * 4;
    float* score= (float*)p; p += 104 * 4;
    int*   nidx = (int*)p;  p += 104 * 4;
    float* wn   = (float*)p;

    const int g = blockIdx.x, t = threadIdx.x;
    const int lane = t & 31, warp = t >> 5;
    const int ne = g_ecnt[g];

    for (int i = t; i < 4096; i += 256) { Wgs[i] = Wg[i]; Wts[i] = Wt[i]; }
    for (int i = t; i < KP1 * 32; i += 256) tile[i] = g_h1p[(size_t)g * KP1 * 32 + i];
    if (t == 0) {
        float s = 0.f;
        for (int k = 0; k < 32; k++) s += pw[k] * pw[k];
        *wn = sqrtf(s);
    }
    if (t < KP1) cnt[t] = 0;
    __syncthreads();

    for (int i = t; i < KP1 * 128; i += 256) {
        int n = i >> 7, c = i & 127;
        float a = 0.f;
        #pragma unroll
        for (int k = 0; k < 32; k++) a += tile[n * 32 + k] * Wgs[k * 128 + c];
        xp[i] = a;
    }
    __syncthreads();
    for (int i = t; i < KP1 * 4; i += 256) {
        int n = i >> 2, h = i & 3;
        float a = 0.f, b = 0.f;
        #pragma unroll
        for (int c = 0; c < 32; c++) {
            float v = xp[n * 128 + h * 32 + c];
            a += v * as_w[h * 32 + c];
            b += v * ad_w[h * 32 + c];
        }
        asv[i] = a; adv[i] = b;
    }
    __syncthreads();
    for (int e = t; e < ne; e += 256) {
        int pk = g_edge2[g * EPG + e];
        int s = pk >> 8, d = pk & 255;
        srcl[e] = (unsigned char)s; dstl[e] = (unsigned char)d;
        atomicAdd(&cnt[d], 1);
        float4 l4;
        l4.x = lrelu(asv[s * 4 + 0] + adv[d * 4 + 0]);
        l4.y = lrelu(asv[s * 4 + 1] + adv[d * 4 + 1]);
        l4.z = lrelu(asv[s * 4 + 2] + adv[d * 4 + 2]);
        l4.w = lrelu(asv[s * 4 + 3] + adv[d * 4 + 3]);
        *(float4*)&lg[e * 4] = l4;
    }
    __syncthreads();
    if (t == 0) {
        int a = 0;
        for (int n = 0; n < KP1; n++) { offs[n] = a; a += cnt[n]; cnt[n] = 0; }
        offs[KP1] = a;
    }
    __syncthreads();
    for (int e = t; e < ne; e += 256) {
        int d = dstl[e];
        eidx[offs[d] + atomicAdd(&cnt[d], 1)] = (unsigned short)e;
    }
    __syncthreads();

    for (int d = warp; d < KP1; d += 8) {
        int o0 = offs[d], dg = offs[d + 1] - o0;
        float sl[4];
        #pragma unroll
        for (int h = 0; h < 4; h++) sl[h] = lrelu(asv[d * 4 + h] + adv[d * 4 + h]);
        int hh = lane & 3;
        float mmax = -1e30f;
        for (int b = lane >> 2; b < dg; b += 8)
            mmax = fmaxf(mmax, lg[eidx[o0 + b] * 4 + hh]);
        for (int m = 4; m < 32; m <<= 1)
            mmax = fmaxf(mmax, __shfl_xor_sync(0xffffffffu, mmax, m));
        float mx[4];
        #pragma unroll
        for (int h = 0; h < 4; h++)
            mx[h] = fmaxf(__shfl_sync(0xffffffffu, mmax, h), sl[h]);
        float md = 0.f;
        for (int b = lane >> 2; b < dg; b += 8) {
            int e = eidx[o0 + b];
            float ex = expf(lg[e * 4 + hh] - mx[hh]);
            lg[e * 4 + hh] = ex;
            md += ex;
        }
        for (int m = 4; m < 32; m <<= 1)
            md += __shfl_xor_sync(0xffffffffu, md, m);
        float den[4], acc[4];
        #pragma unroll
        for (int h = 0; h < 4; h++) {
            float se = expf(sl[h] - mx[h]);
            den[h] = __shfl_sync(0xffffffffu, md, h) + se + 1e-16f;
            acc[h] = se * xp[d * 128 + h * 32 + lane];
        }
        __syncwarp();
        for (int k2 = 0; k2 < dg; k2++) {
            int e = eidx[o0 + k2]; int s = srcl[e];
            float4 ex4 = *(const float4*)&lg[e * 4];
            acc[0] += ex4.x * xp[s * 128 +   0 + lane];
            acc[1] += ex4.y * xp[s * 128 +  32 + lane];
            acc[2] += ex4.z * xp[s * 128 +  64 + lane];
            acc[3] += ex4.w * xp[s * 128 +  96 + lane];
        }
        #pragma unroll
        for (int j = 0; j < 4; j++) {
            float v = acc[j] / den[j] + bg[j * 32 + lane];
            outt[d * 128 + j * 32 + lane] = fmaxf(v, 0.f);
        }
    }
    __syncthreads();

    for (int i = t; i < KP1 * 32; i += 256) {
        int n = i >> 5, o = i & 31;
        float a = bt[o];
        const float* orow = &outt[n * 128];
        #pragma unroll 4
        for (int c = 0; c < 128; c++) a += orow[c] * Wts[c * 32 + o];
        hsh[i] = a;
    }
    __syncthreads();
    if (t < KP1) {
        float s = 0.f;
        #pragma unroll
        for (int o = 0; o < 32; o++) s += hsh[t * 32 + o] * pw[o];
        score[t] = tanhf(s / (*wn));
    }
    __syncthreads();
    if (t < KP1) {
        float sc = score[t]; int r = 0;
        for (int m = 0; m < KP1; m++) {
            float v = score[m];
            r += (v > sc) || (v == sc && m < t);
        }
        nidx[t] = (r < KP2) ? 1 : 0;
    }
    __syncthreads();
    if (t < 32) {
        float m2 = -1e30f, su = 0.f;
        for (int n = 0; n < KP1; n++) if (nidx[n]) {
            float v = hsh[n * 32 + t] * score[n];
            m2 = fmaxf(m2, v); su += v;
        }
        g_gf[g * 64 + t]      = g_g1[g * 64 + t]      + m2;
        g_gf[g * 64 + 32 + t] = g_g1[g * 64 + 32 + t] + su / (float)KP2;
    }
}

// ============================================================================
// Stage 3: MLP 64 -> 256 -> 1024 -> 1. 128 blocks x 4 graphs.
// ============================================================================
__global__ __launch_bounds__(256, 1)
void mlp_kernel(const float* __restrict__ Wl1, const float* __restrict__ bl1,
                const float* __restrict__ Wl2, const float* __restrict__ bl2,
                const float* __restrict__ Wl3, const float* __restrict__ bl3,
                float* __restrict__ out)
{
    __shared__ float gsh[4][64];
    __shared__ float t1[4][256];
    __shared__ float wl3s[1024];
    __shared__ float red[8];
    const int rb = blockIdx.x * 4;
    const int t = threadIdx.x, lane = t & 31, warp = t >> 5;

    for (int i = t; i < 1024; i += 256) wl3s[i] = Wl3[i];
    for (int i = t; i < 4 * 64; i += 256) gsh[i >> 6][i & 63] = g_gf[rb * 64 + i];
    __syncthreads();
    for (int i = t; i < 4 * 256; i += 256) {
        int r = i >> 8, j = i & 255;
        float a = bl1[j];
        #pragma unroll 4
        for (int k = 0; k < 64; k++) a += gsh[r][k] * Wl1[k * 256 + j];
        t1[r][j] = fmaxf(a, 0.f);
    }
    __syncthreads();
    const int r = warp & 3, half = warp >> 2;
    float part = 0.f;
    for (int i = 0; i < 16; i++) {
        int j = half * 512 + i * 32 + lane;
        float a = bl2[j];
        #pragma unroll 4
        for (int k = 0; k < 256; k++) a += t1[r][k] * Wl2[k * 1024 + j];
        part += fmaxf(a, 0.f) * wl3s[j];
    }
    for (int m = 16; m; m >>= 1) part += __shfl_xor_sync(0xffffffffu, part, m);
    if (lane == 0) red[warp] = part;
    __syncthreads();
    if (t < 4) out[rb + t] = red[t] + red[t + 4] + bl3[0];
}

// ============================================================================
extern "C" void kernel_launch(void* const* d_in, const int* in_sizes, int n_in,
                              void* d_out, int out_size)
{
    const float* x   = (const float*)d_in[0];
    const int*   ei  = (const int*)d_in[1];
    // d_in[2] edge_attr (unused), d_in[3] batch (unused)
    const float* Wg1 = (const float*)d_in[4];
    const float* as1 = (const float*)d_in[5];
    const float* ad1 = (const float*)d_in[6];
    const float* bg1 = (const float*)d_in[7];
    const float* Wt1 = (const float*)d_in[8];
    const float* bt1 = (const float*)d_in[9];
    const float* pw1 = (const float*)d_in[10];
    const float* Wg2 = (const float*)d_in[11];
    const float* as2 = (const float*)d_in[12];
    const float* ad2 = (const float*)d_in[13];
    const float* bg2 = (const float*)d_in[14];
    const float* Wt2 = (const float*)d_in[15];
    const float* bt2 = (const float*)d_in[16];
    const float* pw2 = (const float*)d_in[17];
    const float* Wl1 = (const float*)d_in[18];
    const float* bl1 = (const float*)d_in[19];
    const float* Wl2 = (const float*)d_in[20];
    const float* bl2 = (const float*)d_in[21];
    const float* Wl3 = (const float*)d_in[22];
    const float* bl3 = (const float*)d_in[23];
    float* out = (float*)d_out;

    const int SM1B = 201216;   // >= exact 200216 bytes
    const int SM2B = 198144;   // >= exact 197352 bytes
    cudaFuncSetAttribute(stage1_kernel, cudaFuncAttributeMaxDynamicSharedMemorySize, SM1B);
    cudaFuncSetAttribute(stage2_kernel, cudaFuncAttributeMaxDynamicSharedMemorySize, SM2B);

    stage1_kernel<<<NB, 256, SM1B>>>(x, ei, Wg1, as1, ad1, bg1, Wt1, bt1, pw1);
    stage2_kernel<<<NB, 256, SM2B>>>(Wg2, as2, ad2, bg2, Wt2, bt2, pw2);
    mlp_kernel<<<NB / 4, 256>>>(Wl1, bl1, Wl2, bl2, Wl3, bl3, out);
}

// round 2
// speedup vs baseline: 1.1712x; 1.1712x over previous
#include <cuda_runtime.h>
#include <math.h>

#define NB   512
#define NPG  128
#define EPG  2048
#define ETOT 1048576
#define KP1  103
#define KP2  83

__device__ float g_h1p[NB * KP1 * 32];
__device__ int   g_edge2[NB * EPG];
__device__ int   g_ecnt[NB];
__device__ float g_g1[NB * 64];
__device__ float g_gf[NB * 64];

static __device__ __forceinline__ float lrelu(float v) { return v > 0.f ? v : 0.2f * v; }

// ============================================================================
// Stage 1: GAT conv1 + linear + TopK pool1 + readout + edge remap. 512 thr/CTA.
// ============================================================================
__global__ __launch_bounds__(512, 1)
void stage1_kernel(const float* __restrict__ x, const int* __restrict__ ei,
                   const float* __restrict__ Wg, const float* __restrict__ as_w,
                   const float* __restrict__ ad_w, const float* __restrict__ bg,
                   const float* __restrict__ Wt, const float* __restrict__ bt,
                   const float* __restrict__ pw)
{
    extern __shared__ char sm[];
    float* xp    = (float*)sm;           // 16384
    float* outt  = xp + 16384;           // 16384
    float* lg    = outt + 16384;         // 8192 (later hsh)
    float* hsh   = lg;
    float* Wgs   = lg + 8192;            // 1408
    float* Wts   = Wgs + 1408;           // 4096
    float* xs    = Wts + 4096;           // 1408
    float* asv   = xs + 1408;            // 512
    float* adv   = asv + 512;            // 512
    float* asws  = adv + 512;            // 128
    float* adws  = asws + 128;           // 128
    float* score = adws + 128;           // 128
    int*   cnt   = (int*)(score + 128);  // 128
    int*   offs  = cnt + 128;            // 132
    int*   nidx  = offs + 132;           // 128
    int*   masks = nidx + 128;           // 4
    int*   ec    = masks + 4;            // 1
    float* wn    = (float*)(ec + 1);     // 1
    unsigned short* eidx = (unsigned short*)(wn + 1);       // 2048
    unsigned char*  srcl = (unsigned char*)(eidx + 2048);   // 2048
    unsigned char*  dstl = srcl + 2048;                     // 2048

    const int g = blockIdx.x, t = threadIdx.x;
    const int lane = t & 31, warp = t >> 5;

    for (int i = t; i < 11 * 128; i += 512) Wgs[i] = Wg[i];
    for (int i = t; i < 128 * 32; i += 512) Wts[i] = Wt[i];
    for (int i = t; i < 128 * 11; i += 512) xs[i] = x[(size_t)g * NPG * 11 + i];
    if (t < 128) { asws[t] = as_w[t]; adws[t] = ad_w[t]; cnt[t] = 0; }
    if (t == 0) {
        float s = 0.f;
        for (int k = 0; k < 32; k++) s += pw[k] * pw[k];
        *wn = sqrtf(s); *ec = 0;
    }
    __syncthreads();

    // xp = x @ W_g1 (float4 over output channels)
    for (int grp = t; grp < 4096; grp += 512) {
        int n = grp >> 5, cq = grp & 31;
        const float* xr = xs + n * 11;
        float4 a = {0.f, 0.f, 0.f, 0.f};
        const float4* W4 = (const float4*)Wgs;
        #pragma unroll
        for (int k = 0; k < 11; k++) {
            float xv = xr[k];
            float4 w = W4[k * 32 + cq];
            a.x += xv * w.x; a.y += xv * w.y; a.z += xv * w.z; a.w += xv * w.w;
        }
        ((float4*)xp)[grp] = a;
    }
    __syncthreads();

    // per-node per-head attention terms (512 values == 512 threads)
    {
        int n = t >> 2, h = t & 3;
        float a = 0.f, b = 0.f;
        #pragma unroll
        for (int c = 0; c < 32; c++) {
            float v = xp[n * 128 + h * 32 + c];
            a += v * asws[h * 32 + c];
            b += v * adws[h * 32 + c];
        }
        asv[t] = a; adv[t] = b;
    }
    __syncthreads();

    // edges: logits + dst counts
    for (int e = t; e < EPG; e += 512) {
        int s = ei[g * EPG + e] - g * NPG;
        int d = ei[ETOT + g * EPG + e] - g * NPG;
        srcl[e] = (unsigned char)s; dstl[e] = (unsigned char)d;
        atomicAdd(&cnt[d], 1);
        float4 l4;
        l4.x = lrelu(asv[s * 4 + 0] + adv[d * 4 + 0]);
        l4.y = lrelu(asv[s * 4 + 1] + adv[d * 4 + 1]);
        l4.z = lrelu(asv[s * 4 + 2] + adv[d * 4 + 2]);
        l4.w = lrelu(asv[s * 4 + 3] + adv[d * 4 + 3]);
        ((float4*)lg)[e] = l4;
    }
    __syncthreads();
    // exclusive scan of 128 counts (warp 0)
    if (warp == 0) {
        int b = lane * 4;
        int v0 = cnt[b], v1 = cnt[b + 1], v2 = cnt[b + 2], v3 = cnt[b + 3];
        int s = v0 + v1 + v2 + v3;
        int incl = s;
        #pragma unroll
        for (int o = 1; o < 32; o <<= 1) {
            int u = __shfl_up_sync(0xffffffffu, incl, o);
            if (lane >= o) incl += u;
        }
        int base = incl - s;
        offs[b] = base; offs[b + 1] = base + v0;
        offs[b + 2] = base + v0 + v1; offs[b + 3] = base + v0 + v1 + v2;
        if (lane == 31) offs[128] = incl;
        cnt[b] = 0; cnt[b + 1] = 0; cnt[b + 2] = 0; cnt[b + 3] = 0;
    }
    __syncthreads();
    for (int e = t; e < EPG; e += 512) {
        int d = dstl[e];
        eidx[offs[d] + atomicAdd(&cnt[d], 1)] = (unsigned short)e;
    }
    __syncthreads();

    // per-dst softmax + aggregation: one warp per node
    for (int d = warp; d < 128; d += 16) {
        int o0 = offs[d], dg = offs[d + 1] - o0;
        float sl[4];
        #pragma unroll
        for (int h = 0; h < 4; h++) sl[h] = lrelu(asv[d * 4 + h] + adv[d * 4 + h]);
        int hh = lane & 3;
        float mmax = -1e30f;
        for (int b = lane >> 2; b < dg; b += 8)
            mmax = fmaxf(mmax, lg[eidx[o0 + b] * 4 + hh]);
        #pragma unroll
        for (int m = 4; m < 32; m <<= 1)
            mmax = fmaxf(mmax, __shfl_xor_sync(0xffffffffu, mmax, m));
        float mx[4];
        #pragma unroll
        for (int h = 0; h < 4; h++)
            mx[h] = fmaxf(__shfl_sync(0xffffffffu, mmax, h), sl[h]);
        float md = 0.f;
        for (int b = lane >> 2; b < dg; b += 8) {
            int e = eidx[o0 + b];
            float ex = expf(lg[e * 4 + hh] - mx[hh]);
            lg[e * 4 + hh] = ex;
            md += ex;
        }
        #pragma unroll
        for (int m = 4; m < 32; m <<= 1)
            md += __shfl_xor_sync(0xffffffffu, md, m);
        float den[4], acc[4];
        #pragma unroll
        for (int h = 0; h < 4; h++) {
            float se = expf(sl[h] - mx[h]);
            den[h] = __shfl_sync(0xffffffffu, md, h) + se + 1e-16f;
            acc[h] = se * xp[d * 128 + h * 32 + lane];
        }
        __syncwarp();
        for (int k2 = 0; k2 < dg; k2++) {
            int e = eidx[o0 + k2]; int s = srcl[e];
            float4 ex4 = ((const float4*)lg)[e];
            acc[0] += ex4.x * xp[s * 128 +  0 + lane];
            acc[1] += ex4.y * xp[s * 128 + 32 + lane];
            acc[2] += ex4.z * xp[s * 128 + 64 + lane];
            acc[3] += ex4.w * xp[s * 128 + 96 + lane];
        }
        #pragma unroll
        for (int j = 0; j < 4; j++) {
            float v = acc[j] / den[j] + bg[j * 32 + lane];
            outt[d * 128 + j * 32 + lane] = fmaxf(v, 0.f);
        }
    }
    __syncthreads();

    // h = relu(conv) @ W_t1 + b_t1  — register-blocked 4x4 with float4 LDS
    for (int grp = t; grp < 1024; grp += 512) {
        int n = grp >> 3, oq = grp & 7;
        float4 a = ((const float4*)bt)[oq];
        const float4* orow4 = (const float4*)(outt + n * 128);
        const float4* W4 = (const float4*)Wts;
        #pragma unroll 8
        for (int c4 = 0; c4 < 32; c4++) {
            float4 ov = orow4[c4];
            float4 w0 = W4[(c4 * 4 + 0) * 8 + oq];
            float4 w1 = W4[(c4 * 4 + 1) * 8 + oq];
            float4 w2 = W4[(c4 * 4 + 2) * 8 + oq];
            float4 w3 = W4[(c4 * 4 + 3) * 8 + oq];
            a.x += ov.x * w0.x + ov.y * w1.x + ov.z * w2.x + ov.w * w3.x;
            a.y += ov.x * w0.y + ov.y * w1.y + ov.z * w2.y + ov.w * w3.y;
            a.z += ov.x * w0.z + ov.y * w1.z + ov.z * w2.z + ov.w * w3.z;
            a.w += ov.x * w0.w + ov.y * w1.w + ov.z * w2.w + ov.w * w3.w;
        }
        ((float4*)hsh)[grp] = a;
    }
    __syncthreads();

    // pool scores + stable top-K rank
    if (t < 128) {
        float s = 0.f;
        #pragma unroll
        for (int o = 0; o < 32; o++) s += hsh[t * 32 + o] * pw[o];
        score[t] = tanhf(s / (*wn));
    }
    __syncthreads();
    if (t < 128) {
        float sc = score[t]; int r = 0;
        for (int m = 0; m < 128; m++) {
            float v = score[m];
            r += (v > sc) || (v == sc && m < t);
        }
        int keep = (r < KP1);
        unsigned bm = __ballot_sync(0xffffffffu, keep);
        if (lane == 0) masks[warp] = (int)bm;
        nidx[t] = keep;
    }
    __syncthreads();
    if (t < 128) {
        int before = 0;
        for (int w2 = 0; w2 < warp; w2++) before += __popc((unsigned)masks[w2]);
        before += __popc((unsigned)masks[warp] & ((1u << lane) - 1u));
        nidx[t] = nidx[t] ? before : -1;
    }
    __syncthreads();

    // pooled features + g1 readout + remapped edges
    for (int i = t; i < 4096; i += 512) {
        int n = i >> 5, o = i & 31, ni = nidx[n];
        if (ni >= 0) g_h1p[((size_t)g * KP1 + ni) * 32 + o] = hsh[i] * score[n];
    }
    if (t < 32) {
        float m2 = -1e30f, su = 0.f;
        for (int n = 0; n < 128; n++) if (nidx[n] >= 0) {
            float v = hsh[n * 32 + t] * score[n];
            m2 = fmaxf(m2, v); su += v;
        }
        g_g1[g * 64 + t] = m2;
        g_g1[g * 64 + 32 + t] = su / (float)KP1;
    }
    for (int e = t; e < EPG; e += 512) {
        int ns = nidx[srcl[e]], nd = nidx[dstl[e]];
        int valid = (ns >= 0 && nd >= 0);
        unsigned bm = __ballot_sync(0xffffffffu, valid);
        int base;
        if (lane == 0) base = atomicAdd(ec, __popc(bm));
        base = __shfl_sync(0xffffffffu, base, 0);
        if (valid)
            g_edge2[g * EPG + base + __popc(bm & ((1u << lane) - 1u))] = (ns << 8) | nd;
    }
    __syncthreads();
    if (t == 0) g_ecnt[g] = *ec;
}

// ============================================================================
// Stage 2: GAT conv2 + linear + TopK pool2 + readout -> g = g1+g2. 512 thr/CTA.
// ============================================================================
__global__ __launch_bounds__(512, 1)
void stage2_kernel(const float* __restrict__ Wg, const float* __restrict__ as_w,
                   const float* __restrict__ ad_w, const float* __restrict__ bg,
                   const float* __restrict__ Wt, const float* __restrict__ bt,
                   const float* __restrict__ pw)
{
    extern __shared__ char sm[];
    float* tile  = (float*)sm;           // 3296
    float* xp    = tile + 3296;          // 13184
    float* outt  = xp + 13184;           // 13184
    float* lg    = outt + 13184;         // 8192 (later hsh)
    float* hsh   = lg;
    float* Wgs   = lg + 8192;            // 4096
    float* Wts   = Wgs + 4096;           // 4096
    float* asv   = Wts + 4096;           // 416
    float* adv   = asv + 416;            // 416
    float* asws  = adv + 416;            // 128
    float* adws  = asws + 128;           // 128
    float* score = adws + 128;           // 104
    int*   cnt   = (int*)(score + 104);  // 104
    int*   offs  = cnt + 104;            // 104
    int*   nidx  = offs + 104;           // 104
    float* wn    = (float*)(nidx + 104); // 1
    unsigned short* eidx = (unsigned short*)(wn + 1);
    unsigned char*  srcl = (unsigned char*)(eidx + 2048);
    unsigned char*  dstl = srcl + 2048;

    const int g = blockIdx.x, t = threadIdx.x;
    const int lane = t & 31, warp = t >> 5;
    const int ne = g_ecnt[g];

    for (int i = t; i < 4096; i += 512) { Wgs[i] = Wg[i]; Wts[i] = Wt[i]; }
    for (int i = t; i < KP1 * 32; i += 512) tile[i] = g_h1p[(size_t)g * KP1 * 32 + i];
    if (t < 128) { asws[t] = as_w[t]; adws[t] = ad_w[t]; }
    if (t < 104) cnt[t] = 0;
    if (t == 0) {
        float s = 0.f;
        for (int k = 0; k < 32; k++) s += pw[k] * pw[k];
        *wn = sqrtf(s);
    }
    __syncthreads();

    // xp = tile @ W_g2 (4x4 register blocked, float4)
    for (int grp = t; grp < KP1 * 32; grp += 512) {
        int n = grp >> 5, cq = grp & 31;
        float4 a = {0.f, 0.f, 0.f, 0.f};
        const float4* tr4 = (const float4*)(tile + n * 32);
        const float4* W4 = (const float4*)Wgs;
        #pragma unroll
        for (int k4 = 0; k4 < 8; k4++) {
            float4 tv = tr4[k4];
            float4 w0 = W4[(k4 * 4 + 0) * 32 + cq];
            float4 w1 = W4[(k4 * 4 + 1) * 32 + cq];
            float4 w2 = W4[(k4 * 4 + 2) * 32 + cq];
            float4 w3 = W4[(k4 * 4 + 3) * 32 + cq];
            a.x += tv.x * w0.x + tv.y * w1.x + tv.z * w2.x + tv.w * w3.x;
            a.y += tv.x * w0.y + tv.y * w1.y + tv.z * w2.y + tv.w * w3.y;
            a.z += tv.x * w0.z + tv.y * w1.z + tv.z * w2.z + tv.w * w3.z;
            a.w += tv.x * w0.w + tv.y * w1.w + tv.z * w2.w + tv.w * w3.w;
        }
        ((float4*)xp)[grp] = a;
    }
    __syncthreads();
    for (int i = t; i < KP1 * 4; i += 512) {
        int n = i >> 2, h = i & 3;
        float a = 0.f, b = 0.f;
        #pragma unroll
        for (int c = 0; c < 32; c++) {
            float v = xp[n * 128 + h * 32 + c];
            a += v * asws[h * 32 + c];
            b += v * adws[h * 32 + c];
        }
        asv[i] = a; adv[i] = b;
    }
    __syncthreads();
    for (int e = t; e < ne; e += 512) {
        int pk = g_edge2[g * EPG + e];
        int s = pk >> 8, d = pk & 255;
        srcl[e] = (unsigned char)s; dstl[e] = (unsigned char)d;
        atomicAdd(&cnt[d], 1);
        float4 l4;
        l4.x = lrelu(asv[s * 4 + 0] + adv[d * 4 + 0]);
        l4.y = lrelu(asv[s * 4 + 1] + adv[d * 4 + 1]);
        l4.z = lrelu(asv[s * 4 + 2] + adv[d * 4 + 2]);
        l4.w = lrelu(asv[s * 4 + 3] + adv[d * 4 + 3]);
        ((float4*)lg)[e] = l4;
    }
    __syncthreads();
    if (warp == 0) {
        int b = lane * 4;
        int v0 = 0, v1 = 0, v2 = 0, v3 = 0;
        if (b < 104) { v0 = cnt[b]; v1 = cnt[b + 1]; v2 = cnt[b + 2]; v3 = cnt[b + 3]; }
        int s = v0 + v1 + v2 + v3;
        int incl = s;
        #pragma unroll
        for (int o = 1; o < 32; o <<= 1) {
            int u = __shfl_up_sync(0xffffffffu, incl, o);
            if (lane >= o) incl += u;
        }
        int base = incl - s;
        if (b < 104) {
            offs[b] = base; offs[b + 1] = base + v0;
            offs[b + 2] = base + v0 + v1; offs[b + 3] = base + v0 + v1 + v2;
            cnt[b] = 0; cnt[b + 1] = 0; cnt[b + 2] = 0; cnt[b + 3] = 0;
        }
    }
    __syncthreads();
    for (int e = t; e < ne; e += 512) {
        int d = dstl[e];
        eidx[offs[d] + atomicAdd(&cnt[d], 1)] = (unsigned short)e;
    }
    __syncthreads();

    for (int d = warp; d < KP1; d += 16) {
        int o0 = offs[d], dg = offs[d + 1] - o0;
        float sl[4];
        #pragma unroll
        for (int h = 0; h < 4; h++) sl[h] = lrelu(asv[d * 4 + h] + adv[d * 4 + h]);
        int hh = lane & 3;
        float mmax = -1e30f;
        for (int b = lane >> 2; b < dg; b += 8)
            mmax = fmaxf(mmax, lg[eidx[o0 + b] * 4 + hh]);
        #pragma unroll
        for (int m = 4; m < 32; m <<= 1)
            mmax = fmaxf(mmax, __shfl_xor_sync(0xffffffffu, mmax, m));
        float mx[4];
        #pragma unroll
        for (int h = 0; h < 4; h++)
            mx[h] = fmaxf(__shfl_sync(0xffffffffu, mmax, h), sl[h]);
        float md = 0.f;
        for (int b = lane >> 2; b < dg; b += 8) {
            int e = eidx[o0 + b];
            float ex = expf(lg[e * 4 + hh] - mx[hh]);
            lg[e * 4 + hh] = ex;
            md += ex;
        }
        #pragma unroll
        for (int m = 4; m < 32; m <<= 1)
            md += __shfl_xor_sync(0xffffffffu, md, m);
        float den[4], acc[4];
        #pragma unroll
        for (int h = 0; h < 4; h++) {
            float se = expf(sl[h] - mx[h]);
            den[h] = __shfl_sync(0xffffffffu, md, h) + se + 1e-16f;
            acc[h] = se * xp[d * 128 + h * 32 + lane];
        }
        __syncwarp();
        for (int k2 = 0; k2 < dg; k2++) {
            int e = eidx[o0 + k2]; int s = srcl[e];
            float4 ex4 = ((const float4*)lg)[e];
            acc[0] += ex4.x * xp[s * 128 +  0 + lane];
            acc[1] += ex4.y * xp[s * 128 + 32 + lane];
            acc[2] += ex4.z * xp[s * 128 + 64 + lane];
            acc[3] += ex4.w * xp[s * 128 + 96 + lane];
        }
        #pragma unroll
        for (int j = 0; j < 4; j++) {
            float v = acc[j] / den[j] + bg[j * 32 + lane];
            outt[d * 128 + j * 32 + lane] = fmaxf(v, 0.f);
        }
    }
    __syncthreads();

    for (int grp = t; grp < KP1 * 8; grp += 512) {
        int n = grp >> 3, oq = grp & 7;
        float4 a = ((const float4*)bt)[oq];
        const float4* orow4 = (const float4*)(outt + n * 128);
        const float4* W4 = (const float4*)Wts;
        #pragma unroll 8
        for (int c4 = 0; c4 < 32; c4++) {
            float4 ov = orow4[c4];
            float4 w0 = W4[(c4 * 4 + 0) * 8 + oq];
            float4 w1 = W4[(c4 * 4 + 1) * 8 + oq];
            float4 w2 = W4[(c4 * 4 + 2) * 8 + oq];
            float4 w3 = W4[(c4 * 4 + 3) * 8 + oq];
            a.x += ov.x * w0.x + ov.y * w1.x + ov.z * w2.x + ov.w * w3.x;
            a.y += ov.x * w0.y + ov.y * w1.y + ov.z * w2.y + ov.w * w3.y;
            a.z += ov.x * w0.z + ov.y * w1.z + ov.z * w2.z + ov.w * w3.z;
            a.w += ov.x * w0.w + ov.y * w1.w + ov.z * w2.w + ov.w * w3.w;
        }
        ((float4*)hsh)[grp] = a;
    }
    __syncthreads();
    if (t < KP1) {
        float s = 0.f;
        #pragma unroll
        for (int o = 0; o < 32; o++) s += hsh[t * 32 + o] * pw[o];
        score[t] = tanhf(s / (*wn));
    }
    __syncthreads();
    if (t < KP1) {
        float sc = score[t]; int r = 0;
        for (int m = 0; m < KP1; m++) {
            float v = score[m];
            r += (v > sc) || (v == sc && m < t);
        }
        nidx[t] = (r < KP2) ? 1 : 0;
    }
    __syncthreads();
    if (t < 32) {
        float m2 = -1e30f, su = 0.f;
        for (int n = 0; n < KP1; n++) if (nidx[n]) {
            float v = hsh[n * 32 + t] * score[n];
            m2 = fmaxf(m2, v); su += v;
        }
        g_gf[g * 64 + t]      = g_g1[g * 64 + t]      + m2;
        g_gf[g * 64 + 32 + t] = g_g1[g * 64 + 32 + t] + su / (float)KP2;
    }
}

// ============================================================================
// Stage 3: MLP 64 -> 256 -> 1024 -> 1. 64 blocks x 8 graphs, 256 threads.
// ============================================================================
__global__ __launch_bounds__(256, 1)
void mlp_kernel(const float* __restrict__ Wl1, const float* __restrict__ bl1,
                const float* __restrict__ Wl2, const float* __restrict__ bl2,
                const float* __restrict__ Wl3, const float* __restrict__ bl3,
                float* __restrict__ out)
{
    __shared__ float gsh[8][64];
    __shared__ __align__(16) float t1[8][256];
    __shared__ __align__(16) float wl3s[1024];
    __shared__ float redw[8][8];
    const int rb = blockIdx.x * 8;
    const int t = threadIdx.x, lane = t & 31, warp = t >> 5;

    for (int i = t; i < 1024; i += 256) wl3s[i] = Wl3[i];
    for (int i = t; i < 512; i += 256) ((float*)gsh)[i] = g_gf[rb * 64 + i];
    __syncthreads();
    for (int i = t; i < 2048; i += 256) {
        int r = i >> 8, j = i & 255;
        float a = bl1[j];
        #pragma unroll 8
        for (int k = 0; k < 64; k++) a += gsh[r][k] * Wl1[k * 256 + j];
        t1[r][j] = fmaxf(a, 0.f);
    }
    __syncthreads();
    // layer2 (+ fold into Wl3 dot): thread owns 4 consecutive j's for all 8 rows
    const int jg = t;  // j = jg*4
    float4 acc[8];
    {
        float4 b2 = ((const float4*)bl2)[jg];
        #pragma unroll
        for (int r = 0; r < 8; r++) acc[r] = b2;
    }
    const float4* W2 = (const float4*)Wl2;
    for (int k4 = 0; k4 < 64; k4++) {
        float4 w0 = W2[(k4 * 4 + 0) * 256 + jg];
        float4 w1 = W2[(k4 * 4 + 1) * 256 + jg];
        float4 w2 = W2[(k4 * 4 + 2) * 256 + jg];
        float4 w3 = W2[(k4 * 4 + 3) * 256 + jg];
        #pragma unroll
        for (int r = 0; r < 8; r++) {
            float4 tv = ((const float4*)t1[r])[k4];
            acc[r].x += tv.x * w0.x + tv.y * w1.x + tv.z * w2.x + tv.w * w3.x;
            acc[r].y += tv.x * w0.y + tv.y * w1.y + tv.z * w2.y + tv.w * w3.y;
            acc[r].z += tv.x * w0.z + tv.y * w1.z + tv.z * w2.z + tv.w * w3.z;
            acc[r].w += tv.x * w0.w + tv.y * w1.w + tv.z * w2.w + tv.w * w3.w;
        }
    }
    float4 w3v = ((const float4*)wl3s)[jg];
    #pragma unroll
    for (int r = 0; r < 8; r++) {
        float p = fmaxf(acc[r].x, 0.f) * w3v.x + fmaxf(acc[r].y, 0.f) * w3v.y +
                  fmaxf(acc[r].z, 0.f) * w3v.z + fmaxf(acc[r].w, 0.f) * w3v.w;
        #pragma unroll
        for (int m = 16; m; m >>= 1) p += __shfl_xor_sync(0xffffffffu, p, m);
        if (lane == 0) redw[r][warp] = p;
    }
    __syncthreads();
    if (t < 8) {
        float s = bl3[0];
        #pragma unroll
        for (int w2 = 0; w2 < 8; w2++) s += redw[t][w2];
        out[rb + t] = s;
    }
}

// ============================================================================
extern "C" void kernel_launch(void* const* d_in, const int* in_sizes, int n_in,
                              void* d_out, int out_size)
{
    const float* x   = (const float*)d_in[0];
    const int*   ei  = (const int*)d_in[1];
    const float* Wg1 = (const float*)d_in[4];
    const float* as1 = (const float*)d_in[5];
    const float* ad1 = (const float*)d_in[6];
    const float* bg1 = (const float*)d_in[7];
    const float* Wt1 = (const float*)d_in[8];
    const float* bt1 = (const float*)d_in[9];
    const float* pw1 = (const float*)d_in[10];
    const float* Wg2 = (const float*)d_in[11];
    const float* as2 = (const float*)d_in[12];
    const float* ad2 = (const float*)d_in[13];
    const float* bg2 = (const float*)d_in[14];
    const float* Wt2 = (const float*)d_in[15];
    const float* bt2 = (const float*)d_in[16];
    const float* pw2 = (const float*)d_in[17];
    const float* Wl1 = (const float*)d_in[18];
    const float* bl1 = (const float*)d_in[19];
    const float* Wl2 = (const float*)d_in[20];
    const float* bl2 = (const float*)d_in[21];
    const float* Wl3 = (const float*)d_in[22];
    const float* bl3 = (const float*)d_in[23];
    float* out = (float*)d_out;

    const int SM1B = 206912;
    const int SM2B = 198416;
    cudaFuncSetAttribute(stage1_kernel, cudaFuncAttributeMaxDynamicSharedMemorySize, SM1B);
    cudaFuncSetAttribute(stage2_kernel, cudaFuncAttributeMaxDynamicSharedMemorySize, SM2B);

    stage1_kernel<<<NB, 512, SM1B>>>(x, ei, Wg1, as1, ad1, bg1, Wt1, bt1, pw1);
    stage2_kernel<<<NB, 512, SM2B>>>(Wg2, as2, ad2, bg2, Wt2, bt2, pw2);
    mlp_kernel<<<NB / 8, 256>>>(Wl1, bl1, Wl2, bl2, Wl3, bl3, out);
}

// round 3
// speedup vs baseline: 2.2506x; 1.9216x over previous
#include <cuda_runtime.h>
#include <math.h>

#define NB   512
#define NPG  128
#define EPG  2048
#define ETOT 1048576
#define KP1  103
#define KP2  83

__device__ float g_h1p[NB * KP1 * 32];
__device__ int   g_edge2[NB * EPG];
__device__ int   g_ecnt[NB];
__device__ float g_g1[NB * 64];
__device__ float g_gf[NB * 64];

static __device__ __forceinline__ float lrelu(float v) { return v > 0.f ? v : 0.2f * v; }

// ============================================================================
// Stage 1. 256 threads, 2 CTAs/SM. smem ~111 KB.
// ============================================================================
__global__ __launch_bounds__(256, 2)
void stage1_kernel(const float* __restrict__ x, const int* __restrict__ ei,
                   const float* __restrict__ Wg, const float* __restrict__ as_w,
                   const float* __restrict__ ad_w, const float* __restrict__ bg,
                   const float* __restrict__ Wt, const float* __restrict__ bt,
                   const float* __restrict__ pw)
{
    extern __shared__ __align__(16) char sm[];
    float* xp    = (float*)sm;               // 16384 f
    float* hsh   = xp + 16384;               // 4096 f
    float* Wts   = hsh + 4096;               // 4096 f
    float* asv   = Wts + 4096;               // 512 f
    float* adv   = asv + 512;                // 512 f
    float* bg_s  = adv + 512;                // 128 f
    float* bt_s  = bg_s + 128;               // 32 f
    float* score = bt_s + 32;                // 128 f
    float* scratch = score + 128;            // 8*128 f
    int*   cnt   = (int*)(scratch + 1024);   // 128
    int*   offs  = cnt + 128;                // 129
    int*   nidx  = offs + 129;               // 128
    int*   masks = nidx + 128;               // 4
    int*   ec    = masks + 4;                // 1
    unsigned char* eidx = (unsigned char*)(ec + 1);  // 2048

    const int g = blockIdx.x, t = threadIdx.x;
    const int lane = t & 31, warp = t >> 5;
    const int gbase = g * EPG;

    for (int i = t; i < 4096; i += 256) Wts[i] = Wt[i];
    if (t < 128) { bg_s[t] = bg[t]; cnt[t] = 0; }
    if (t < 32) bt_s[t] = bt[t];
    if (t == 0) *ec = 0;
    __syncthreads();

    // xp = x @ W_g1 : grp = n*32 + cq (float4 over channels)
    for (int grp = t; grp < 4096; grp += 256) {
        int n = grp >> 5, cq = grp & 31;
        const float* xr = x + (size_t)(g * NPG + n) * 11;
        const float4* W4 = (const float4*)Wg;
        float4 a = {0.f, 0.f, 0.f, 0.f};
        #pragma unroll
        for (int k = 0; k < 11; k++) {
            float xv = __ldg(xr + k);
            float4 w = __ldg(W4 + k * 32 + cq);
            a.x += xv * w.x; a.y += xv * w.y; a.z += xv * w.z; a.w += xv * w.w;
        }
        ((float4*)xp)[grp] = a;
    }
    __syncthreads();

    // attention terms asv/adv [node][head]
    for (int i = t; i < 512; i += 256) {
        int n = i >> 2, h = i & 3;
        float a = 0.f, b = 0.f;
        #pragma unroll
        for (int c = 0; c < 32; c++) {
            float v = xp[n * 128 + h * 32 + c];
            a += v * __ldg(as_w + h * 32 + c);
            b += v * __ldg(ad_w + h * 32 + c);
        }
        asv[i] = a; adv[i] = b;
    }
    __syncthreads();

    // CSR build: count, scan, place (src stored as uchar)
    for (int e = t; e < EPG; e += 256) {
        int d = ei[ETOT + gbase + e] - g * NPG;
        atomicAdd(&cnt[d], 1);
    }
    __syncthreads();
    if (warp == 0) {
        int b = lane * 4;
        int v0 = cnt[b], v1 = cnt[b + 1], v2 = cnt[b + 2], v3 = cnt[b + 3];
        int s = v0 + v1 + v2 + v3, incl = s;
        #pragma unroll
        for (int o = 1; o < 32; o <<= 1) {
            int u = __shfl_up_sync(0xffffffffu, incl, o);
            if (lane >= o) incl += u;
        }
        int base = incl - s;
        offs[b] = base; offs[b + 1] = base + v0;
        offs[b + 2] = base + v0 + v1; offs[b + 3] = base + v0 + v1 + v2;
        if (lane == 31) offs[128] = incl;
        cnt[b] = 0; cnt[b + 1] = 0; cnt[b + 2] = 0; cnt[b + 3] = 0;
    }
    __syncthreads();
    for (int e = t; e < EPG; e += 256) {
        int s = ei[gbase + e] - g * NPG;
        int d = ei[ETOT + gbase + e] - g * NPG;
        eidx[offs[d] + atomicAdd(&cnt[d], 1)] = (unsigned char)s;
    }
    __syncthreads();

    // per-dst: fused softmax (no max-shift) + aggregation + per-node W_t GEMM
    float* scr = scratch + warp * 128;
    for (int d = warp; d < 128; d += 8) {
        int o0 = offs[d], dg = offs[d + 1] - o0;
        // self term: lanes 0..3 hold heads
        float sl = asv[d * 4 + (lane & 3)] + adv[d * 4 + (lane & 3)];
        float se = __expf(lrelu(sl));
        float den[4], acc[4];
        #pragma unroll
        for (int h = 0; h < 4; h++) {
            den[h] = __shfl_sync(0xffffffffu, se, h);
            acc[h] = den[h] * xp[d * 128 + h * 32 + lane];
        }
        float4 advd = ((const float4*)adv)[d];
        for (int base = 0; base < dg; base += 32) {
            int m = min(32, dg - base);
            if (lane < m) {
                int s = eidx[o0 + base + lane];
                float4 av = ((const float4*)asv)[s];
                float4 exv;
                exv.x = __expf(lrelu(av.x + advd.x));
                exv.y = __expf(lrelu(av.y + advd.y));
                exv.z = __expf(lrelu(av.z + advd.z));
                exv.w = __expf(lrelu(av.w + advd.w));
                ((float4*)scr)[lane] = exv;
            }
            __syncwarp();
            for (int k = 0; k < m; k++) {
                int s = eidx[o0 + base + k];
                float4 ex = ((const float4*)scr)[k];
                acc[0] += ex.x * xp[s * 128 +  0 + lane];
                acc[1] += ex.y * xp[s * 128 + 32 + lane];
                acc[2] += ex.z * xp[s * 128 + 64 + lane];
                acc[3] += ex.w * xp[s * 128 + 96 + lane];
                den[0] += ex.x; den[1] += ex.y; den[2] += ex.z; den[3] += ex.w;
            }
            __syncwarp();
        }
        // conv row (post-relu) -> scratch
        #pragma unroll
        for (int j = 0; j < 4; j++)
            scr[j * 32 + lane] = fmaxf(acc[j] / (den[j] + 1e-16f) + bg_s[j * 32 + lane], 0.f);
        __syncwarp();
        // h[d][lane] = bt[lane] + row . Wt[:,lane]
        float a = bt_s[lane];
        #pragma unroll 8
        for (int c4 = 0; c4 < 32; c4++) {
            float4 r = ((const float4*)scr)[c4];
            a += r.x * Wts[(c4 * 4 + 0) * 32 + lane];
            a += r.y * Wts[(c4 * 4 + 1) * 32 + lane];
            a += r.z * Wts[(c4 * 4 + 2) * 32 + lane];
            a += r.w * Wts[(c4 * 4 + 3) * 32 + lane];
        }
        hsh[d * 32 + lane] = a;
        __syncwarp();
    }
    __syncthreads();

    // scores + stable top-K
    if (t < 128) {
        float s = 0.f, ss = 0.f;
        #pragma unroll
        for (int o = 0; o < 32; o++) {
            float w = __ldg(pw + o);
            s += hsh[t * 32 + o] * w; ss += w * w;
        }
        score[t] = tanhf(s / sqrtf(ss));
    }
    __syncthreads();
    if (t < 128) {
        float sc = score[t]; int r = 0;
        for (int m = 0; m < 128; m++) {
            float v = score[m];
            r += (v > sc) || (v == sc && m < t);
        }
        int keep = (r < KP1);
        unsigned bm = __ballot_sync(0xffffffffu, keep);
        if (lane == 0) masks[warp] = (int)bm;
        nidx[t] = keep;
    }
    __syncthreads();
    if (t < 128) {
        int before = 0;
        for (int w2 = 0; w2 < warp; w2++) before += __popc((unsigned)masks[w2]);
        before += __popc((unsigned)masks[warp] & ((1u << lane) - 1u));
        nidx[t] = nidx[t] ? before : -1;
    }
    __syncthreads();

    for (int i = t; i < 4096; i += 256) {
        int n = i >> 5, o = i & 31, ni = nidx[n];
        if (ni >= 0) g_h1p[((size_t)g * KP1 + ni) * 32 + o] = hsh[i] * score[n];
    }
    if (t < 32) {
        float m2 = -1e30f, su = 0.f;
        for (int n = 0; n < 128; n++) if (nidx[n] >= 0) {
            float v = hsh[n * 32 + t] * score[n];
            m2 = fmaxf(m2, v); su += v;
        }
        g_g1[g * 64 + t] = m2;
        g_g1[g * 64 + 32 + t] = su / (float)KP1;
    }
    for (int e = t; e < EPG; e += 256) {
        int ns = nidx[ei[gbase + e] - g * NPG];
        int nd = nidx[ei[ETOT + gbase + e] - g * NPG];
        int valid = (ns >= 0 && nd >= 0);
        unsigned bm = __ballot_sync(0xffffffffu, valid);
        int base;
        if (lane == 0) base = atomicAdd(ec, __popc(bm));
        base = __shfl_sync(0xffffffffu, base, 0);
        if (valid)
            g_edge2[gbase + base + __popc(bm & ((1u << lane) - 1u))] = (ns << 8) | nd;
    }
    __syncthreads();
    if (t == 0) g_ecnt[g] = *ec;
}

// ============================================================================
// Stage 2. 256 threads, 2 CTAs/SM. smem ~94 KB.
// ============================================================================
__global__ __launch_bounds__(256, 2)
void stage2_kernel(const float* __restrict__ Wg, const float* __restrict__ as_w,
                   const float* __restrict__ ad_w, const float* __restrict__ bg,
                   const float* __restrict__ Wt, const float* __restrict__ bt,
                   const float* __restrict__ pw)
{
    extern __shared__ __align__(16) char sm[];
    float* xp    = (float*)sm;               // 13184 f
    float* hsh   = xp + 13184;               // 3296 f
    float* Wts   = hsh + 3296;               // 4096 f
    float* asv   = Wts + 4096;               // 416 f
    float* adv   = asv + 416;                // 416 f
    float* bg_s  = adv + 416;                // 128 f
    float* bt_s  = bg_s + 128;               // 32 f
    float* score = bt_s + 32;                // 104 f
    float* scratch = score + 104;            // 1024 f
    int*   cnt   = (int*)(scratch + 1024);   // 104
    int*   offs  = cnt + 104;                // 105
    int*   nidx  = offs + 105;               // 104
    unsigned char* eidx = (unsigned char*)(nidx + 104);  // 2048

    const int g = blockIdx.x, t = threadIdx.x;
    const int lane = t & 31, warp = t >> 5;
    const int ne = g_ecnt[g];

    for (int i = t; i < 4096; i += 256) Wts[i] = Wt[i];
    if (t < 128) bg_s[t] = bg[t];
    if (t < 32) bt_s[t] = bt[t];
    if (t < 104) cnt[t] = 0;
    __syncthreads();

    // xp = h1p @ W_g2 (register-blocked float4)
    for (int grp = t; grp < KP1 * 32; grp += 256) {
        int n = grp >> 5, cq = grp & 31;
        const float4* tr4 = (const float4*)(g_h1p + ((size_t)g * KP1 + n) * 32);
        const float4* W4 = (const float4*)Wg;
        float4 a = {0.f, 0.f, 0.f, 0.f};
        #pragma unroll
        for (int k4 = 0; k4 < 8; k4++) {
            float4 tv = __ldg(tr4 + k4);
            float4 w0 = __ldg(W4 + (k4 * 4 + 0) * 32 + cq);
            float4 w1 = __ldg(W4 + (k4 * 4 + 1) * 32 + cq);
            float4 w2 = __ldg(W4 + (k4 * 4 + 2) * 32 + cq);
            float4 w3 = __ldg(W4 + (k4 * 4 + 3) * 32 + cq);
            a.x += tv.x * w0.x + tv.y * w1.x + tv.z * w2.x + tv.w * w3.x;
            a.y += tv.x * w0.y + tv.y * w1.y + tv.z * w2.y + tv.w * w3.y;
            a.z += tv.x * w0.z + tv.y * w1.z + tv.z * w2.z + tv.w * w3.z;
            a.w += tv.x * w0.w + tv.y * w1.w + tv.z * w2.w + tv.w * w3.w;
        }
        ((float4*)xp)[grp] = a;
    }
    __syncthreads();

    for (int i = t; i < KP1 * 4; i += 256) {
        int n = i >> 2, h = i & 3;
        float a = 0.f, b = 0.f;
        #pragma unroll
        for (int c = 0; c < 32; c++) {
            float v = xp[n * 128 + h * 32 + c];
            a += v * __ldg(as_w + h * 32 + c);
            b += v * __ldg(ad_w + h * 32 + c);
        }
        asv[i] = a; adv[i] = b;
    }
    __syncthreads();

    for (int e = t; e < ne; e += 256)
        atomicAdd(&cnt[g_edge2[g * EPG + e] & 255], 1);
    __syncthreads();
    if (warp == 0 && lane < 26) {
        int b = lane * 4;
        int v0 = cnt[b], v1 = cnt[b + 1], v2 = cnt[b + 2], v3 = cnt[b + 3];
        int s = v0 + v1 + v2 + v3, incl = s;
        #pragma unroll
        for (int o = 1; o < 32; o <<= 1) {
            int u = __shfl_up_sync(0x03ffffffu, incl, o);
            if (lane >= o) incl += u;
        }
        int base = incl - s;
        offs[b] = base; offs[b + 1] = base + v0;
        offs[b + 2] = base + v0 + v1; offs[b + 3] = base + v0 + v1 + v2;
        cnt[b] = 0; cnt[b + 1] = 0; cnt[b + 2] = 0; cnt[b + 3] = 0;
    }
    __syncthreads();
    for (int e = t; e < ne; e += 256) {
        int pk = g_edge2[g * EPG + e];
        int d = pk & 255;
        eidx[offs[d] + atomicAdd(&cnt[d], 1)] = (unsigned char)(pk >> 8);
    }
    __syncthreads();

    float* scr = scratch + warp * 128;
    for (int d = warp; d < KP1; d += 8) {
        int o0 = offs[d], dg = offs[d + 1] - o0;
        float sl = asv[d * 4 + (lane & 3)] + adv[d * 4 + (lane & 3)];
        float se = __expf(lrelu(sl));
        float den[4], acc[4];
        #pragma unroll
        for (int h = 0; h < 4; h++) {
            den[h] = __shfl_sync(0xffffffffu, se, h);
            acc[h] = den[h] * xp[d * 128 + h * 32 + lane];
        }
        float4 advd = ((const float4*)adv)[d];
        for (int base = 0; base < dg; base += 32) {
            int m = min(32, dg - base);
            if (lane < m) {
                int s = eidx[o0 + base + lane];
                float4 av = ((const float4*)asv)[s];
                float4 exv;
                exv.x = __expf(lrelu(av.x + advd.x));
                exv.y = __expf(lrelu(av.y + advd.y));
                exv.z = __expf(lrelu(av.z + advd.z));
                exv.w = __expf(lrelu(av.w + advd.w));
                ((float4*)scr)[lane] = exv;
            }
            __syncwarp();
            for (int k = 0; k < m; k++) {
                int s = eidx[o0 + base + k];
                float4 ex = ((const float4*)scr)[k];
                acc[0] += ex.x * xp[s * 128 +  0 + lane];
                acc[1] += ex.y * xp[s * 128 + 32 + lane];
                acc[2] += ex.z * xp[s * 128 + 64 + lane];
                acc[3] += ex.w * xp[s * 128 + 96 + lane];
                den[0] += ex.x; den[1] += ex.y; den[2] += ex.z; den[3] += ex.w;
            }
            __syncwarp();
        }
        #pragma unroll
        for (int j = 0; j < 4; j++)
            scr[j * 32 + lane] = fmaxf(acc[j] / (den[j] + 1e-16f) + bg_s[j * 32 + lane], 0.f);
        __syncwarp();
        float a = bt_s[lane];
        #pragma unroll 8
        for (int c4 = 0; c4 < 32; c4++) {
            float4 r = ((const float4*)scr)[c4];
            a += r.x * Wts[(c4 * 4 + 0) * 32 + lane];
            a += r.y * Wts[(c4 * 4 + 1) * 32 + lane];
            a += r.z * Wts[(c4 * 4 + 2) * 32 + lane];
            a += r.w * Wts[(c4 * 4 + 3) * 32 + lane];
        }
        hsh[d * 32 + lane] = a;
        __syncwarp();
    }
    __syncthreads();

    if (t < KP1) {
        float s = 0.f, ss = 0.f;
        #pragma unroll
        for (int o = 0; o < 32; o++) {
            float w = __ldg(pw + o);
            s += hsh[t * 32 + o] * w; ss += w * w;
        }
        score[t] = tanhf(s / sqrtf(ss));
    }
    __syncthreads();
    if (t < KP1) {
        float sc = score[t]; int r = 0;
        for (int m = 0; m < KP1; m++) {
            float v = score[m];
            r += (v > sc) || (v == sc && m < t);
        }
        nidx[t] = (r < KP2) ? 1 : 0;
    }
    __syncthreads();
    if (t < 32) {
        float m2 = -1e30f, su = 0.f;
        for (int n = 0; n < KP1; n++) if (nidx[n]) {
            float v = hsh[n * 32 + t] * score[n];
            m2 = fmaxf(m2, v); su += v;
        }
        g_gf[g * 64 + t]      = g_g1[g * 64 + t]      + m2;
        g_gf[g * 64 + 32 + t] = g_g1[g * 64 + 32 + t] + su / (float)KP2;
    }
}

// ============================================================================
// Stage 3: MLP 64 -> 256 -> 1024 -> 1. 64 blocks x 8 graphs, 256 threads.
// ============================================================================
__global__ __launch_bounds__(256, 1)
void mlp_kernel(const float* __restrict__ Wl1, const float* __restrict__ bl1,
                const float* __restrict__ Wl2, const float* __restrict__ bl2,
                const float* __restrict__ Wl3, const float* __restrict__ bl3,
                float* __restrict__ out)
{
    __shared__ float gsh[8][64];
    __shared__ __align__(16) float t1[8][256];
    __shared__ __align__(16) float wl3s[1024];
    __shared__ float redw[8][8];
    const int rb = blockIdx.x * 8;
    const int t = threadIdx.x, lane = t & 31, warp = t >> 5;

    for (int i = t; i < 1024; i += 256) wl3s[i] = Wl3[i];
    for (int i = t; i < 512; i += 256) ((float*)gsh)[i] = g_gf[rb * 64 + i];
    __syncthreads();
    for (int i = t; i < 2048; i += 256) {
        int r = i >> 8, j = i & 255;
        float a = bl1[j];
        #pragma unroll 8
        for (int k = 0; k < 64; k++) a += gsh[r][k] * Wl1[k * 256 + j];
        t1[r][j] = fmaxf(a, 0.f);
    }
    __syncthreads();
    const int jg = t;
    float4 acc[8];
    {
        float4 b2 = ((const float4*)bl2)[jg];
        #pragma unroll
        for (int r = 0; r < 8; r++) acc[r] = b2;
    }
    const float4* W2 = (const float4*)Wl2;
    for (int k4 = 0; k4 < 64; k4++) {
        float4 w0 = W2[(k4 * 4 + 0) * 256 + jg];
        float4 w1 = W2[(k4 * 4 + 1) * 256 + jg];
        float4 w2 = W2[(k4 * 4 + 2) * 256 + jg];
        float4 w3 = W2[(k4 * 4 + 3) * 256 + jg];
        #pragma unroll
        for (int r = 0; r < 8; r++) {
            float4 tv = ((const float4*)t1[r])[k4];
            acc[r].x += tv.x * w0.x + tv.y * w1.x + tv.z * w2.x + tv.w * w3.x;
            acc[r].y += tv.x * w0.y + tv.y * w1.y + tv.z * w2.y + tv.w * w3.y;
            acc[r].z += tv.x * w0.z + tv.y * w1.z + tv.z * w2.z + tv.w * w3.z;
            acc[r].w += tv.x * w0.w + tv.y * w1.w + tv.z * w2.w + tv.w * w3.w;
        }
    }
    float4 w3v = ((const float4*)wl3s)[jg];
    #pragma unroll
    for (int r = 0; r < 8; r++) {
        float p = fmaxf(acc[r].x, 0.f) * w3v.x + fmaxf(acc[r].y, 0.f) * w3v.y +
                  fmaxf(acc[r].z, 0.f) * w3v.z + fmaxf(acc[r].w, 0.f) * w3v.w;
        #pragma unroll
        for (int m = 16; m; m >>= 1) p += __shfl_xor_sync(0xffffffffu, p, m);
        if (lane == 0) redw[r][warp] = p;
    }
    __syncthreads();
    if (t < 8) {
        float s = bl3[0];
        #pragma unroll
        for (int w2 = 0; w2 < 8; w2++) s += redw[t][w2];
        out[rb + t] = s;
    }
}

// ============================================================================
extern "C" void kernel_launch(void* const* d_in, const int* in_sizes, int n_in,
                              void* d_out, int out_size)
{
    const float* x   = (const float*)d_in[0];
    const int*   ei  = (const int*)d_in[1];
    const float* Wg1 = (const float*)d_in[4];
    const float* as1 = (const float*)d_in[5];
    const float* ad1 = (const float*)d_in[6];
    const float* bg1 = (const float*)d_in[7];
    const float* Wt1 = (const float*)d_in[8];
    const float* bt1 = (const float*)d_in[9];
    const float* pw1 = (const float*)d_in[10];
    const float* Wg2 = (const float*)d_in[11];
    const float* as2 = (const float*)d_in[12];
    const float* ad2 = (const float*)d_in[13];
    const float* bg2 = (const float*)d_in[14];
    const float* Wt2 = (const float*)d_in[15];
    const float* bt2 = (const float*)d_in[16];
    const float* pw2 = (const float*)d_in[17];
    const float* Wl1 = (const float*)d_in[18];
    const float* bl1 = (const float*)d_in[19];
    const float* Wl2 = (const float*)d_in[20];
    const float* bl2 = (const float*)d_in[21];
    const float* Wl3 = (const float*)d_in[22];
    const float* bl3 = (const float*)d_in[23];
    float* out = (float*)d_out;

    // stage1: floats 26912 + ints 390 + 2048 uchar = 111,256 B
    const int SM1B = 111360;
    // stage2: floats 22696 + ints 313 + 2048 uchar = 94,084 B
    const int SM2B = 94208;
    cudaFuncSetAttribute(stage1_kernel, cudaFuncAttributeMaxDynamicSharedMemorySize, SM1B);
    cudaFuncSetAttribute(stage2_kernel, cudaFuncAttributeMaxDynamicSharedMemorySize, SM2B);

    stage1_kernel<<<NB, 256, SM1B>>>(x, ei, Wg1, as1, ad1, bg1, Wt1, bt1, pw1);
    stage2_kernel<<<NB, 256, SM2B>>>(Wg2, as2, ad2, bg2, Wt2, bt2, pw2);
    mlp_kernel<<<NB / 8, 256>>>(Wl1, bl1, Wl2, bl2, Wl3, bl3, out);
}

// round 7
// speedup vs baseline: 2.4001x; 1.0664x over previous
#include <cuda_runtime.h>
#include <cuda_fp16.h>
#include <math.h>

#define NB   512
#define NPG  128
#define EPG  2048
#define ETOT 1048576
#define KP1  103
#define KP2  83

__device__ float g_h1p[NB * KP1 * 32];
__device__ float g_hsh[NB * NPG * 32];     // per-stage h rows (reused by stage2)
__device__ int   g_edge2[NB * EPG];
__device__ int   g_ecnt[NB];
__device__ float g_g1[NB * 64];
__device__ float g_gf[NB * 64];

static __device__ __forceinline__ float lrelu(float v) { return v > 0.f ? v : 0.2f * v; }

// ============================================================================
// Stage 1. 384 threads, 2 CTAs/SM, smem 112640 B. fp32 everywhere except
// precomputed edge exp values (fp16).
// ============================================================================
__global__ __launch_bounds__(384, 2)
void stage1_kernel(const float* __restrict__ x, const int* __restrict__ ei,
                   const float* __restrict__ Wg, const float* __restrict__ as_w,
                   const float* __restrict__ ad_w, const float* __restrict__ bg,
                   const float* __restrict__ Wt, const float* __restrict__ bt,
                   const float* __restrict__ pw)
{
    extern __shared__ __align__(16) char sm[];
    float4*  xp4   = (float4*)sm;                       // [4096]  65536 B
    __half2* lg2   = (__half2*)(sm + 65536);            // [4096]  16384 B
    float4*  Wts4  = (float4*)(sm + 81920);             // [1024]  16384 B
    float*   asv   = (float*)(sm + 98304);              // 512 f
    float*   adv   = (float*)(sm + 100352);             // 512 f
    float*   score = (float*)(sm + 102400);             // 128 f
    float*   scratch = (float*)(sm + 102912);           // 12*128 f (also Wgs temp)
    int*     cnt   = (int*)(sm + 109056);               // 128
    int*     offs  = (int*)(sm + 109568);               // 129
    unsigned char* srcl = (unsigned char*)(sm + 110084);// 2048
    // aliases into xp4 region (valid only after aggregation)
    float* red   = (float*)sm;                          // 12*32
    float* red2  = (float*)(sm + 1536);                 // 12*32
    int*   nidx  = (int*)(sm + 3072);                   // 128
    int*   masks = (int*)(sm + 3584);                   // 4
    int*   ec    = (int*)(sm + 3600);                   // 1

    const int g = blockIdx.x, t = threadIdx.x;
    const int lane = t & 31, warp = t >> 5;
    const int gbase = g * EPG;
    float* Wgs = scratch;  // 1408 floats, live only during xp phase

    for (int i = t; i < 1024; i += 384) {
        int c4 = i >> 5, o = i & 31;
        Wts4[i] = make_float4(__ldg(Wt + (4 * c4 + 0) * 32 + o),
                              __ldg(Wt + (4 * c4 + 1) * 32 + o),
                              __ldg(Wt + (4 * c4 + 2) * 32 + o),
                              __ldg(Wt + (4 * c4 + 3) * 32 + o));
    }
    for (int i = t; i < 1408; i += 384) Wgs[i] = __ldg(Wg + i);
    if (t < 128) cnt[t] = 0;
    __syncthreads();

    // xp (permuted float4 layout) + fused asv/adv
    {
        float asw0 = __ldg(as_w + lane), asw1 = __ldg(as_w + 32 + lane);
        float asw2 = __ldg(as_w + 64 + lane), asw3 = __ldg(as_w + 96 + lane);
        float adw0 = __ldg(ad_w + lane), adw1 = __ldg(ad_w + 32 + lane);
        float adw2 = __ldg(ad_w + 64 + lane), adw3 = __ldg(ad_w + 96 + lane);
        for (int n = warp; n < 128; n += 12) {
            const float* xr = x + (size_t)(g * NPG + n) * 11;
            float4 a = {0.f, 0.f, 0.f, 0.f};
            #pragma unroll
            for (int k = 0; k < 11; k++) {
                float xv = __ldg(xr + k);
                a.x += xv * Wgs[k * 128 + lane];
                a.y += xv * Wgs[k * 128 + 32 + lane];
                a.z += xv * Wgs[k * 128 + 64 + lane];
                a.w += xv * Wgs[k * 128 + 96 + lane];
            }
            xp4[n * 32 + lane] = a;
            float4 pa = {a.x * asw0, a.y * asw1, a.z * asw2, a.w * asw3};
            float4 pb = {a.x * adw0, a.y * adw1, a.z * adw2, a.w * adw3};
            #pragma unroll
            for (int off = 16; off; off >>= 1) {
                pa.x += __shfl_xor_sync(0xffffffffu, pa.x, off);
                pa.y += __shfl_xor_sync(0xffffffffu, pa.y, off);
                pa.z += __shfl_xor_sync(0xffffffffu, pa.z, off);
                pa.w += __shfl_xor_sync(0xffffffffu, pa.w, off);
                pb.x += __shfl_xor_sync(0xffffffffu, pb.x, off);
                pb.y += __shfl_xor_sync(0xffffffffu, pb.y, off);
                pb.z += __shfl_xor_sync(0xffffffffu, pb.z, off);
                pb.w += __shfl_xor_sync(0xffffffffu, pb.w, off);
            }
            if (lane == 0) { ((float4*)asv)[n] = pa; ((float4*)adv)[n] = pb; }
        }
    }
    __syncthreads();

    // CSR: count, scan, place (+ precompute edge exp into fp16)
    for (int e = t; e < EPG; e += 384)
        atomicAdd(&cnt[ei[ETOT + gbase + e] - g * NPG], 1);
    __syncthreads();
    if (warp == 0) {
        int b = lane * 4;
        int v0 = cnt[b], v1 = cnt[b + 1], v2 = cnt[b + 2], v3 = cnt[b + 3];
        int s = v0 + v1 + v2 + v3, incl = s;
        #pragma unroll
        for (int o = 1; o < 32; o <<= 1) {
            int u = __shfl_up_sync(0xffffffffu, incl, o);
            if (lane >= o) incl += u;
        }
        int base = incl - s;
        offs[b] = base; offs[b + 1] = base + v0;
        offs[b + 2] = base + v0 + v1; offs[b + 3] = base + v0 + v1 + v2;
        if (lane == 31) offs[128] = incl;
        cnt[b] = 0; cnt[b + 1] = 0; cnt[b + 2] = 0; cnt[b + 3] = 0;
    }
    __syncthreads();
    for (int e = t; e < EPG; e += 384) {
        int s = ei[gbase + e] - g * NPG;
        int d = ei[ETOT + gbase + e] - g * NPG;
        int pos = offs[d] + atomicAdd(&cnt[d], 1);
        srcl[pos] = (unsigned char)s;
        float4 av = ((const float4*)asv)[s];
        float4 dv = ((const float4*)adv)[d];
        lg2[2 * pos]     = __floats2half2_rn(__expf(lrelu(av.x + dv.x)),
                                             __expf(lrelu(av.y + dv.y)));
        lg2[2 * pos + 1] = __floats2half2_rn(__expf(lrelu(av.z + dv.z)),
                                             __expf(lrelu(av.w + dv.w)));
    }
    __syncthreads();

    // per-dst aggregation + W_t GEMM + score (fused)
    {
        float4 bgv = make_float4(__ldg(bg + lane), __ldg(bg + 32 + lane),
                                 __ldg(bg + 64 + lane), __ldg(bg + 96 + lane));
        float btl = __ldg(bt + lane);
        float pwl = __ldg(pw + lane);
        float ssn = pwl * pwl;
        #pragma unroll
        for (int off = 16; off; off >>= 1) ssn += __shfl_xor_sync(0xffffffffu, ssn, off);
        float pwinv = rsqrtf(ssn);
        float* scr = scratch + warp * 128;
        float4* scr4 = (float4*)scr;
        for (int d = warp; d < 128; d += 12) {
            int o0 = offs[d], dg = offs[d + 1] - o0;
            float slv = asv[d * 4 + (lane & 3)] + adv[d * 4 + (lane & 3)];
            float sev = __expf(lrelu(slv));
            float4 den;
            den.x = __shfl_sync(0xffffffffu, sev, 0);
            den.y = __shfl_sync(0xffffffffu, sev, 1);
            den.z = __shfl_sync(0xffffffffu, sev, 2);
            den.w = __shfl_sync(0xffffffffu, sev, 3);
            float4 xv = xp4[d * 32 + lane];
            float4 acc = {den.x * xv.x, den.y * xv.y, den.z * xv.z, den.w * xv.w};
            #pragma unroll 4
            for (int k = 0; k < dg; k++) {
                int s = srcl[o0 + k];
                float2 f0 = __half22float2(lg2[2 * (o0 + k)]);
                float2 f1 = __half22float2(lg2[2 * (o0 + k) + 1]);
                float4 xs = xp4[s * 32 + lane];
                acc.x += f0.x * xs.x; acc.y += f0.y * xs.y;
                acc.z += f1.x * xs.z; acc.w += f1.y * xs.w;
                den.x += f0.x; den.y += f0.y; den.z += f1.x; den.w += f1.y;
            }
            float4 r;
            r.x = fmaxf(acc.x / (den.x + 1e-16f) + bgv.x, 0.f);
            r.y = fmaxf(acc.y / (den.y + 1e-16f) + bgv.y, 0.f);
            r.z = fmaxf(acc.z / (den.z + 1e-16f) + bgv.z, 0.f);
            r.w = fmaxf(acc.w / (den.w + 1e-16f) + bgv.w, 0.f);
            scr[lane] = r.x; scr[32 + lane] = r.y;
            scr[64 + lane] = r.z; scr[96 + lane] = r.w;
            __syncwarp();
            float a = btl;
            #pragma unroll 8
            for (int c4 = 0; c4 < 32; c4++) {
                float4 rr = scr4[c4];
                float4 w = Wts4[c4 * 32 + lane];
                a += rr.x * w.x + rr.y * w.y + rr.z * w.z + rr.w * w.w;
            }
            g_hsh[(size_t)g * 4096 + d * 32 + lane] = a;
            float p = a * pwl;
            #pragma unroll
            for (int off = 16; off; off >>= 1) p += __shfl_xor_sync(0xffffffffu, p, off);
            if (lane == 0) score[d] = tanhf(p * pwinv);
            __syncwarp();
        }
    }
    __syncthreads();   // xp4 dead; aliases live

    // stable top-K rank + compaction indices
    if (t < 128) {
        float sc = score[t]; int r = 0;
        for (int m = 0; m < 128; m++) {
            float v = score[m];
            r += (v > sc) || (v == sc && m < t);
        }
        int keep = (r < KP1);
        unsigned bm = __ballot_sync(0xffffffffu, keep);
        if (lane == 0) masks[warp] = (int)bm;
        nidx[t] = keep;
    }
    if (t == 383) *ec = 0;
    __syncthreads();
    if (t < 128) {
        int before = 0;
        for (int w2 = 0; w2 < warp; w2++) before += __popc((unsigned)masks[w2]);
        before += __popc((unsigned)masks[warp] & ((1u << lane) - 1u));
        nidx[t] = nidx[t] ? before : -1;
    }
    __syncthreads();

    // pooled features + partial readout
    {
        int o = t & 31, grp = t >> 5;
        float m2 = -1e30f, su = 0.f;
        for (int n = grp; n < 128; n += 12) {
            int ni = nidx[n];
            if (ni >= 0) {
                float v = g_hsh[(size_t)g * 4096 + n * 32 + o] * score[n];
                m2 = fmaxf(m2, v); su += v;
                g_h1p[((size_t)g * KP1 + ni) * 32 + o] = v;
            }
        }
        red[grp * 32 + o] = m2; red2[grp * 32 + o] = su;
    }
    // edge remap
    for (int e = t; e < EPG; e += 384) {
        int ns = nidx[ei[gbase + e] - g * NPG];
        int nd = nidx[ei[ETOT + gbase + e] - g * NPG];
        int valid = (ns >= 0 && nd >= 0);
        unsigned bm = __ballot_sync(0xffffffffu, valid);
        int base;
        if (lane == 0) base = atomicAdd(ec, __popc(bm));
        base = __shfl_sync(0xffffffffu, base, 0);
        if (valid)
            g_edge2[gbase + base + __popc(bm & ((1u << lane) - 1u))] = (ns << 8) | nd;
    }
    __syncthreads();
    if (t < 32) {
        float m2 = -1e30f, su = 0.f;
        #pragma unroll
        for (int k = 0; k < 12; k++) {
            m2 = fmaxf(m2, red[k * 32 + t]); su += red2[k * 32 + t];
        }
        g_g1[g * 64 + t] = m2;
        g_g1[g * 64 + 32 + t] = su / (float)KP1;
    }
    if (t == 0) g_ecnt[g] = *ec;
}

// ============================================================================
// Stage 2. 384 threads, 2 CTAs/SM, smem 98304 B.
// ============================================================================
__global__ __launch_bounds__(384, 2)
void stage2_kernel(const float* __restrict__ Wg, const float* __restrict__ as_w,
                   const float* __restrict__ ad_w, const float* __restrict__ bg,
                   const float* __restrict__ Wt, const float* __restrict__ bt,
                   const float* __restrict__ pw)
{
    extern __shared__ __align__(16) char sm[];
    float4*  xp4   = (float4*)sm;                       // [103*32] 52736 B
    __half2* lg2   = (__half2*)(sm + 52736);            // 16384 B (Wg2p temp first)
    float4*  Wg2p  = (float4*)(sm + 52736);
    float4*  Wts4  = (float4*)(sm + 69120);             // 16384 B
    float*   asv   = (float*)(sm + 85504);              // 412 f (pad 1664)
    float*   adv   = (float*)(sm + 87168);              // 1664 B
    float*   score = (float*)(sm + 88832);              // 416 B
    float*   scratch = (float*)(sm + 89248);            // 6144 B
    int*     cnt   = (int*)(sm + 95392);                // 104
    int*     offs  = (int*)(sm + 95808);                // 105
    unsigned char* srcl = (unsigned char*)(sm + 96228); // 2048
    float* red   = (float*)sm;
    float* red2  = (float*)(sm + 1536);
    int*   nidx  = (int*)(sm + 3072);                   // 104

    const int g = blockIdx.x, t = threadIdx.x;
    const int lane = t & 31, warp = t >> 5;
    const int ne = g_ecnt[g];

    for (int i = t; i < 1024; i += 384) {
        int c4 = i >> 5, o = i & 31;
        Wts4[i] = make_float4(__ldg(Wt + (4 * c4 + 0) * 32 + o),
                              __ldg(Wt + (4 * c4 + 1) * 32 + o),
                              __ldg(Wt + (4 * c4 + 2) * 32 + o),
                              __ldg(Wt + (4 * c4 + 3) * 32 + o));
        int k = i >> 5, l = i & 31;
        Wg2p[i] = make_float4(__ldg(Wg + k * 128 + l),
                              __ldg(Wg + k * 128 + 32 + l),
                              __ldg(Wg + k * 128 + 64 + l),
                              __ldg(Wg + k * 128 + 96 + l));
    }
    if (t < 104) cnt[t] = 0;
    __syncthreads();

    // xp + fused asv/adv
    {
        float asw0 = __ldg(as_w + lane), asw1 = __ldg(as_w + 32 + lane);
        float asw2 = __ldg(as_w + 64 + lane), asw3 = __ldg(as_w + 96 + lane);
        float adw0 = __ldg(ad_w + lane), adw1 = __ldg(ad_w + 32 + lane);
        float adw2 = __ldg(ad_w + 64 + lane), adw3 = __ldg(ad_w + 96 + lane);
        for (int n = warp; n < KP1; n += 12) {
            float hv = __ldg(g_h1p + ((size_t)g * KP1 + n) * 32 + lane);
            float4 a = {0.f, 0.f, 0.f, 0.f};
            #pragma unroll
            for (int k = 0; k < 32; k++) {
                float tv = __shfl_sync(0xffffffffu, hv, k);
                float4 w = Wg2p[k * 32 + lane];
                a.x += tv * w.x; a.y += tv * w.y; a.z += tv * w.z; a.w += tv * w.w;
            }
            xp4[n * 32 + lane] = a;
            float4 pa = {a.x * asw0, a.y * asw1, a.z * asw2, a.w * asw3};
            float4 pb = {a.x * adw0, a.y * adw1, a.z * adw2, a.w * adw3};
            #pragma unroll
            for (int off = 16; off; off >>= 1) {
                pa.x += __shfl_xor_sync(0xffffffffu, pa.x, off);
                pa.y += __shfl_xor_sync(0xffffffffu, pa.y, off);
                pa.z += __shfl_xor_sync(0xffffffffu, pa.z, off);
                pa.w += __shfl_xor_sync(0xffffffffu, pa.w, off);
                pb.x += __shfl_xor_sync(0xffffffffu, pb.x, off);
                pb.y += __shfl_xor_sync(0xffffffffu, pb.y, off);
                pb.z += __shfl_xor_sync(0xffffffffu, pb.z, off);
                pb.w += __shfl_xor_sync(0xffffffffu, pb.w, off);
            }
            if (lane == 0) { ((float4*)asv)[n] = pa; ((float4*)adv)[n] = pb; }
        }
    }
    __syncthreads();

    for (int e = t; e < ne; e += 384)
        atomicAdd(&cnt[g_edge2[g * EPG + e] & 255], 1);
    __syncthreads();
    if (warp == 0 && lane < 26) {
        int b = lane * 4;
        int v0 = cnt[b], v1 = cnt[b + 1], v2 = cnt[b + 2], v3 = cnt[b + 3];
        int s = v0 + v1 + v2 + v3, incl = s;
        #pragma unroll
        for (int o = 1; o < 32; o <<= 1) {
            int u = __shfl_up_sync(0x03ffffffu, incl, o);
            if (lane >= o) incl += u;
        }
        int base = incl - s;
        offs[b] = base; offs[b + 1] = base + v0;
        offs[b + 2] = base + v0 + v1; offs[b + 3] = base + v0 + v1 + v2;
        cnt[b] = 0; cnt[b + 1] = 0; cnt[b + 2] = 0; cnt[b + 3] = 0;
    }
    __syncthreads();
    for (int e = t; e < ne; e += 384) {
        int pk = g_edge2[g * EPG + e];
        int s = pk >> 8, d = pk & 255;
        int pos = offs[d] + atomicAdd(&cnt[d], 1);
        srcl[pos] = (unsigned char)s;
        float4 av = ((const float4*)asv)[s];
        float4 dv = ((const float4*)adv)[d];
        lg2[2 * pos]     = __floats2half2_rn(__expf(lrelu(av.x + dv.x)),
                                             __expf(lrelu(av.y + dv.y)));
        lg2[2 * pos + 1] = __floats2half2_rn(__expf(lrelu(av.z + dv.z)),
                                             __expf(lrelu(av.w + dv.w)));
    }
    __syncthreads();

    {
        float4 bgv = make_float4(__ldg(bg + lane), __ldg(bg + 32 + lane),
                                 __ldg(bg + 64 + lane), __ldg(bg + 96 + lane));
        float btl = __ldg(bt + lane);
        float pwl = __ldg(pw + lane);
        float ssn = pwl * pwl;
        #pragma unroll
        for (int off = 16; off; off >>= 1) ssn += __shfl_xor_sync(0xffffffffu, ssn, off);
        float pwinv = rsqrtf(ssn);
        float* scr = scratch + warp * 128;
        float4* scr4 = (float4*)scr;
        for (int d = warp; d < KP1; d += 12) {
            int o0 = offs[d], dg = offs[d + 1] - o0;
            float slv = asv[d * 4 + (lane & 3)] + adv[d * 4 + (lane & 3)];
            float sev = __expf(lrelu(slv));
            float4 den;
            den.x = __shfl_sync(0xffffffffu, sev, 0);
            den.y = __shfl_sync(0xffffffffu, sev, 1);
            den.z = __shfl_sync(0xffffffffu, sev, 2);
            den.w = __shfl_sync(0xffffffffu, sev, 3);
            float4 xv = xp4[d * 32 + lane];
            float4 acc = {den.x * xv.x, den.y * xv.y, den.z * xv.z, den.w * xv.w};
            #pragma unroll 4
            for (int k = 0; k < dg; k++) {
                int s = srcl[o0 + k];
                float2 f0 = __half22float2(lg2[2 * (o0 + k)]);
                float2 f1 = __half22float2(lg2[2 * (o0 + k) + 1]);
                float4 xs = xp4[s * 32 + lane];
                acc.x += f0.x * xs.x; acc.y += f0.y * xs.y;
                acc.z += f1.x * xs.z; acc.w += f1.y * xs.w;
                den.x += f0.x; den.y += f0.y; den.z += f1.x; den.w += f1.y;
            }
            float4 r;
            r.x = fmaxf(acc.x / (den.x + 1e-16f) + bgv.x, 0.f);
            r.y = fmaxf(acc.y / (den.y + 1e-16f) + bgv.y, 0.f);
            r.z = fmaxf(acc.z / (den.z + 1e-16f) + bgv.z, 0.f);
            r.w = fmaxf(acc.w / (den.w + 1e-16f) + bgv.w, 0.f);
            scr[lane] = r.x; scr[32 + lane] = r.y;
            scr[64 + lane] = r.z; scr[96 + lane] = r.w;
            __syncwarp();
            float a = btl;
            #pragma unroll 8
            for (int c4 = 0; c4 < 32; c4++) {
                float4 rr = scr4[c4];
                float4 w = Wts4[c4 * 32 + lane];
                a += rr.x * w.x + rr.y * w.y + rr.z * w.z + rr.w * w.w;
            }
            g_hsh[(size_t)g * 4096 + d * 32 + lane] = a;
            float p = a * pwl;
            #pragma unroll
            for (int off = 16; off; off >>= 1) p += __shfl_xor_sync(0xffffffffu, p, off);
            if (lane == 0) score[d] = tanhf(p * pwinv);
            __syncwarp();
        }
    }
    __syncthreads();

    if (t < KP1) {
        float sc = score[t]; int r = 0;
        for (int m = 0; m < KP1; m++) {
            float v = score[m];
            r += (v > sc) || (v == sc && m < t);
        }
        nidx[t] = (r < KP2) ? 1 : 0;
    }
    __syncthreads();
    {
        int o = t & 31, grp = t >> 5;
        float m2 = -1e30f, su = 0.f;
        for (int n = grp; n < KP1; n += 12) {
            if (nidx[n]) {
                float v = g_hsh[(size_t)g * 4096 + n * 32 + o] * score[n];
                m2 = fmaxf(m2, v); su += v;
            }
        }
        red[grp * 32 + o] = m2; red2[grp * 32 + o] = su;
    }
    __syncthreads();
    if (t < 32) {
        float m2 = -1e30f, su = 0.f;
        #pragma unroll
        for (int k = 0; k < 12; k++) {
            m2 = fmaxf(m2, red[k * 32 + t]); su += red2[k * 32 + t];
        }
        g_gf[g * 64 + t]      = g_g1[g * 64 + t]      + m2;
        g_gf[g * 64 + 32 + t] = g_g1[g * 64 + 32 + t] + su / (float)KP2;
    }
}

// ============================================================================
// Stage 3: MLP 64 -> 256 -> 1024 -> 1. 64 blocks x 8 graphs.
// ============================================================================
__global__ __launch_bounds__(256, 1)
void mlp_kernel(const float* __restrict__ Wl1, const float* __restrict__ bl1,
                const float* __restrict__ Wl2, const float* __restrict__ bl2,
                const float* __restrict__ Wl3, const float* __restrict__ bl3,
                float* __restrict__ out)
{
    __shared__ float gsh[8][64];
    __shared__ __align__(16) float t1[8][256];
    __shared__ __align__(16) float wl3s[1024];
    __shared__ float redw[8][8];
    const int rb = blockIdx.x * 8;
    const int t = threadIdx.x, lane = t & 31, warp = t >> 5;

    for (int i = t; i < 1024; i += 256) wl3s[i] = Wl3[i];
    for (int i = t; i < 512; i += 256) ((float*)gsh)[i] = g_gf[rb * 64 + i];
    __syncthreads();
    for (int i = t; i < 2048; i += 256) {
        int r = i >> 8, j = i & 255;
        float a = bl1[j];
        #pragma unroll 8
        for (int k = 0; k < 64; k++) a += gsh[r][k] * Wl1[k * 256 + j];
        t1[r][j] = fmaxf(a, 0.f);
    }
    __syncthreads();
    const int jg = t;
    float4 acc[8];
    {
        float4 b2 = ((const float4*)bl2)[jg];
        #pragma unroll
        for (int r = 0; r < 8; r++) acc[r] = b2;
    }
    const float4* W2 = (const float4*)Wl2;
    for (int k4 = 0; k4 < 64; k4++) {
        float4 w0 = W2[(k4 * 4 + 0) * 256 + jg];
        float4 w1 = W2[(k4 * 4 + 1) * 256 + jg];
        float4 w2 = W2[(k4 * 4 + 2) * 256 + jg];
        float4 w3 = W2[(k4 * 4 + 3) * 256 + jg];
        #pragma unroll
        for (int r = 0; r < 8; r++) {
            float4 tv = ((const float4*)t1[r])[k4];
            acc[r].x += tv.x * w0.x + tv.y * w1.x + tv.z * w2.x + tv.w * w3.x;
            acc[r].y += tv.x * w0.y + tv.y * w1.y + tv.z * w2.y + tv.w * w3.y;
            acc[r].z += tv.x * w0.z + tv.y * w1.z + tv.z * w2.z + tv.w * w3.z;
            acc[r].w += tv.x * w0.w + tv.y * w1.w + tv.z * w2.w + tv.w * w3.w;
        }
    }
    float4 w3v = ((const float4*)wl3s)[jg];
    #pragma unroll
    for (int r = 0; r < 8; r++) {
        float p = fmaxf(acc[r].x, 0.f) * w3v.x + fmaxf(acc[r].y, 0.f) * w3v.y +
                  fmaxf(acc[r].z, 0.f) * w3v.z + fmaxf(acc[r].w, 0.f) * w3v.w;
        #pragma unroll
        for (int m = 16; m; m >>= 1) p += __shfl_xor_sync(0xffffffffu, p, m);
        if (lane == 0) redw[r][warp] = p;
    }
    __syncthreads();
    if (t < 8) {
        float s = bl3[0];
        #pragma unroll
        for (int w2 = 0; w2 < 8; w2++) s += redw[t][w2];
        out[rb + t] = s;
    }
}

// ============================================================================
extern "C" void kernel_launch(void* const* d_in, const int* in_sizes, int n_in,
                              void* d_out, int out_size)
{
    const float* x   = (const float*)d_in[0];
    const int*   ei  = (const int*)d_in[1];
    const float* Wg1 = (const float*)d_in[4];
    const float* as1 = (const float*)d_in[5];
    const float* ad1 = (const float*)d_in[6];
    const float* bg1 = (const float*)d_in[7];
    const float* Wt1 = (const float*)d_in[8];
    const float* bt1 = (const float*)d_in[9];
    const float* pw1 = (const float*)d_in[10];
    const float* Wg2 = (const float*)d_in[11];
    const float* as2 = (const float*)d_in[12];
    const float* ad2 = (const float*)d_in[13];
    const float* bg2 = (const float*)d_in[14];
    const float* Wt2 = (const float*)d_in[15];
    const float* bt2 = (const float*)d_in[16];
    const float* pw2 = (const float*)d_in[17];
    const float* Wl1 = (const float*)d_in[18];
    const float* bl1 = (const float*)d_in[19];
    const float* Wl2 = (const float*)d_in[20];
    const float* bl2 = (const float*)d_in[21];
    const float* Wl3 = (const float*)d_in[22];
    const float* bl3 = (const float*)d_in[23];
    float* out = (float*)d_out;

    const int SM1B = 112640;
    const int SM2B = 98304;
    cudaFuncSetAttribute(stage1_kernel, cudaFuncAttributeMaxDynamicSharedMemorySize, SM1B);
    cudaFuncSetAttribute(stage2_kernel, cudaFuncAttributeMaxDynamicSharedMemorySize, SM2B);

    stage1_kernel<<<NB, 384, SM1B>>>(x, ei, Wg1, as1, ad1, bg1, Wt1, bt1, pw1);
    stage2_kernel<<<NB, 384, SM2B>>>(Wg2, as2, ad2, bg2, Wt2, bt2, pw2);
    mlp_kernel<<<NB / 8, 256>>>(Wl1, bl1, Wl2, bl2, Wl3, bl3, out);
}